// round 2
// baseline (speedup 1.0000x reference)
#include <cuda_runtime.h>
#include <math.h>

#define DIM    7168
#define NEXP   256
#define TOPKN  8
#define NGRP   8
#define TOPG   4
#define NTOK   16384

#define BM   128
#define BN   128
#define KC   16
#define PADW 132

// Scratch for logits (16384 * 256 * 4B = 16 MB). Device-global: allocation-free.
__device__ __align__(16) float g_logits[(size_t)NTOK * NEXP];

// ---------------------------------------------------------------------------
// packed f32x2 helpers (ptxas will not auto-fuse; PTX-only path)
// ---------------------------------------------------------------------------
__device__ __forceinline__ unsigned long long dup_f32x2(float v) {
    unsigned long long r;
    asm("mov.b64 %0, {%1, %1};" : "=l"(r) : "f"(v));
    return r;
}
__device__ __forceinline__ void fma_f32x2(unsigned long long& d,
                                          unsigned long long a,
                                          unsigned long long b) {
    asm("fma.rn.f32x2 %0, %1, %2, %0;" : "+l"(d) : "l"(a), "l"(b));
}
// d = a*b + c (non-accumulating form)
__device__ __forceinline__ unsigned long long fma3_f32x2(unsigned long long a,
                                                         unsigned long long b,
                                                         unsigned long long c) {
    unsigned long long d;
    asm("fma.rn.f32x2 %0, %1, %2, %3;" : "=l"(d) : "l"(a), "l"(b), "l"(c));
    return d;
}
__device__ __forceinline__ unsigned long long add_f32x2(unsigned long long a,
                                                        unsigned long long b) {
    unsigned long long d;
    asm("add.rn.f32x2 %0, %1, %2;" : "=l"(d) : "l"(a), "l"(b));
    return d;
}
__device__ __forceinline__ float2 unpack_f32x2(unsigned long long v) {
    float2 r;
    asm("mov.b64 {%0, %1}, %2;" : "=f"(r.x), "=f"(r.y) : "l"(v));
    return r;
}

#define NEG1X2 0xBF800000BF800000ULL   // packed {-1.0f, -1.0f}

// ---------------------------------------------------------------------------
// GEMM: logits[t][e] = dot(x[t], w[e]),  fp32, f32x2 packed FMA.
// Accuracy: 32-term chunk accumulators folded into a master via Fast2Sum
// (error-free transform); fold residual becomes next chunk's seed. Logit
// error ~eps*4 instead of eps*60 for a 7168-long serial chain.
// CTA tile 128x128, 256 threads, 8x8 micro-tile. Double-buffered smem.
// ---------------------------------------------------------------------------
#define STORE_TILE(buf) do {                                   \
    int kk = ldKq * 4;                                         \
    xs[(buf)][kk+0][ldTok]    = rx0.x;                         \
    xs[(buf)][kk+1][ldTok]    = rx0.y;                         \
    xs[(buf)][kk+2][ldTok]    = rx0.z;                         \
    xs[(buf)][kk+3][ldTok]    = rx0.w;                         \
    xs[(buf)][kk+0][ldTok+64] = rx1.x;                         \
    xs[(buf)][kk+1][ldTok+64] = rx1.y;                         \
    xs[(buf)][kk+2][ldTok+64] = rx1.z;                         \
    xs[(buf)][kk+3][ldTok+64] = rx1.w;                         \
    ws[(buf)][kk+0][ldTok]    = rw0.x;                         \
    ws[(buf)][kk+1][ldTok]    = rw0.y;                         \
    ws[(buf)][kk+2][ldTok]    = rw0.z;                         \
    ws[(buf)][kk+3][ldTok]    = rw0.w;                         \
    ws[(buf)][kk+0][ldTok+64] = rw1.x;                         \
    ws[(buf)][kk+1][ldTok+64] = rw1.y;                         \
    ws[(buf)][kk+2][ldTok+64] = rw1.z;                         \
    ws[(buf)][kk+3][ldTok+64] = rw1.w;                         \
} while (0)

__global__ void __launch_bounds__(256, 1)
gemm_logits_kernel(const float* __restrict__ x, const float* __restrict__ w)
{
    __shared__ __align__(16) float xs[2][KC][PADW];
    __shared__ __align__(16) float ws[2][KC][PADW];

    const int bm = blockIdx.x;
    const int bn = blockIdx.y;
    const int t  = threadIdx.x;

    const int ldTok = t >> 2;   // 0..63
    const int ldKq  = t & 3;

    const float* xb = x + (size_t)(bm * BM) * DIM;
    const float* wb = w + (size_t)(bn * BN) * DIM;

    const int tx = t & 15;      // token-pair group
    const int ty = t >> 4;      // expert group

    unsigned long long acc[8][4];   // current chunk (seeded with prior fold residual)
    unsigned long long hi[8][4];    // master sum
    #pragma unroll
    for (int j = 0; j < 8; j++)
        #pragma unroll
        for (int i = 0; i < 4; i++) { acc[j][i] = 0ULL; hi[j][i] = 0ULL; }

    float4 rx0, rx1, rw0, rw1;

    // prologue: stage 0
    {
        const size_t o0 = (size_t)ldTok * DIM + (size_t)ldKq * 4;
        const size_t o1 = (size_t)(ldTok + 64) * DIM + (size_t)ldKq * 4;
        rx0 = *reinterpret_cast<const float4*>(xb + o0);
        rx1 = *reinterpret_cast<const float4*>(xb + o1);
        rw0 = *reinterpret_cast<const float4*>(wb + o0);
        rw1 = *reinterpret_cast<const float4*>(wb + o1);
    }
    STORE_TILE(0);
    __syncthreads();

    const int nIter = DIM / KC;   // 448
    for (int it = 0; it < nIter; ++it) {
        const int cur = it & 1;

        if (it + 1 < nIter) {
            const size_t kofs = (size_t)(it + 1) * KC + (size_t)ldKq * 4;
            rx0 = *reinterpret_cast<const float4*>(xb + (size_t)ldTok * DIM + kofs);
            rx1 = *reinterpret_cast<const float4*>(xb + (size_t)(ldTok + 64) * DIM + kofs);
            rw0 = *reinterpret_cast<const float4*>(wb + (size_t)ldTok * DIM + kofs);
            rw1 = *reinterpret_cast<const float4*>(wb + (size_t)(ldTok + 64) * DIM + kofs);
        }

        #pragma unroll
        for (int k = 0; k < KC; k++) {
            const float* xr = &xs[cur][k][tx * 8];
            ulonglong2 xpA = *reinterpret_cast<const ulonglong2*>(xr);
            ulonglong2 xpB = *reinterpret_cast<const ulonglong2*>(xr + 4);
            const float* wr = &ws[cur][k][ty * 8];
            float4 wA = *reinterpret_cast<const float4*>(wr);
            float4 wB = *reinterpret_cast<const float4*>(wr + 4);
            float wv[8] = {wA.x, wA.y, wA.z, wA.w, wB.x, wB.y, wB.z, wB.w};
            #pragma unroll
            for (int j = 0; j < 8; j++) {
                unsigned long long wd = dup_f32x2(wv[j]);
                fma_f32x2(acc[j][0], xpA.x, wd);
                fma_f32x2(acc[j][1], xpA.y, wd);
                fma_f32x2(acc[j][2], xpB.x, wd);
                fma_f32x2(acc[j][3], xpB.y, wd);
            }
        }

        // Fast2Sum fold every 32 k-steps: hi' = hi + acc (rounded),
        // residual = acc - (hi' - hi) seeds the next chunk.
        if (it & 1) {
            #pragma unroll
            for (int j = 0; j < 8; j++)
                #pragma unroll
                for (int i = 0; i < 4; i++) {
                    unsigned long long s  = add_f32x2(hi[j][i], acc[j][i]);
                    unsigned long long d1 = fma3_f32x2(hi[j][i], NEG1X2, s);   // s - hi
                    acc[j][i] = fma3_f32x2(d1, NEG1X2, acc[j][i]);             // acc - d1
                    hi[j][i]  = s;
                }
        }

        if (it + 1 < nIter) STORE_TILE(cur ^ 1);
        __syncthreads();
    }

    // final: hi + residual
    const int trow = bm * BM + tx * 8;
    const int ecol = bn * BN + ty * 8;
    #pragma unroll
    for (int i = 0; i < 4; i++) {
        float2 p[8];
        #pragma unroll
        for (int j = 0; j < 8; j++)
            p[j] = unpack_f32x2(add_f32x2(hi[j][i], acc[j][i]));
        float4* q0 = reinterpret_cast<float4*>(&g_logits[(size_t)(trow + 2*i) * NEXP + ecol]);
        q0[0] = make_float4(p[0].x, p[1].x, p[2].x, p[3].x);
        q0[1] = make_float4(p[4].x, p[5].x, p[6].x, p[7].x);
        float4* q1 = reinterpret_cast<float4*>(&g_logits[(size_t)(trow + 2*i + 1) * NEXP + ecol]);
        q1[0] = make_float4(p[0].y, p[1].y, p[2].y, p[3].y);
        q1[1] = make_float4(p[4].y, p[5].y, p[6].y, p[7].y);
    }
}

// ---------------------------------------------------------------------------
// Accurate exp (~2 ulp), immune to -use_fast_math (no libm expf).
// Cody-Waite: k*ln2_hi exact (12-bit hi, |k|<=44); degree-7 Taylor on
// |r|<=0.3466 (remainder 5e-9 rel).
// ---------------------------------------------------------------------------
__device__ __forceinline__ float exp_acc(float xin) {
    float xc = fminf(fmaxf(xin, -30.0f), 30.0f);
    float k = rintf(xc * 1.4426950408889634f);
    float r = fmaf(k, -0.693359375f, xc);
    r = fmaf(k, 2.12194440054690e-4f, r);
    float p = 1.98412698e-4f;
    p = fmaf(p, r, 1.38888889e-3f);
    p = fmaf(p, r, 8.33333333e-3f);
    p = fmaf(p, r, 4.16666667e-2f);
    p = fmaf(p, r, 1.66666667e-1f);
    p = fmaf(p, r, 5.0e-1f);
    p = fmaf(p, r, 1.0f);
    p = fmaf(p, r, 1.0f);
    int ik = (int)k;
    float sc2 = __int_as_float((ik + 127) << 23);
    return p * sc2;
}

// ---------------------------------------------------------------------------
// Epilogue: one CTA (256 threads) per token.
// ---------------------------------------------------------------------------
__global__ void __launch_bounds__(256)
gate_epilogue_kernel(const float* __restrict__ bias,
                     float* __restrict__ out_w,
                     float* __restrict__ out_idx,
                     int write_idx)
{
    const int t    = blockIdx.x;
    const int e    = threadIdx.x;
    const int lane = e & 31;
    const int wid  = e >> 5;      // warp == expert group (32 experts/group)

    __shared__ float sh_sc[NEXP];
    __shared__ float sh_val[NEXP];
    __shared__ float sh_gs[NGRP];
    __shared__ float sh_rv[8];
    __shared__ int   sh_ri[8];
    __shared__ int   sh_sel[TOPKN];
    __shared__ int   sh_win;
    __shared__ unsigned sh_keep;
    __shared__ float sh_wsum;

    const float logit = g_logits[(size_t)t * NEXP + e];
    const float sc = __fdiv_rn(1.0f, 1.0f + exp_acc(-logit));
    const float s  = sc + bias[e];
    sh_sc[e] = sc;

    // --- per-group top-2 sum (warp reduce) ---
    float v1 = s, v2 = -INFINITY;
    #pragma unroll
    for (int o = 16; o > 0; o >>= 1) {
        float u1 = __shfl_down_sync(0xffffffffu, v1, o);
        float u2 = __shfl_down_sync(0xffffffffu, v2, o);
        float hi = fmaxf(v1, u1);
        float lo = fminf(v1, u1);
        float wsec = (v1 >= u1) ? v2 : u2;
        v1 = hi;
        v2 = fmaxf(lo, wsec);
    }
    if (lane == 0) sh_gs[wid] = v1 + v2;
    __syncthreads();

    // --- top-4 groups (ties -> lower index) ---
    if (e == 0) {
        unsigned keep = 0;
        bool used[NGRP] = {false, false, false, false, false, false, false, false};
        for (int r = 0; r < TOPG; r++) {
            float best = -INFINITY; int bi = 0;
            for (int g = 0; g < NGRP; g++) {
                if (!used[g] && sh_gs[g] > best) { best = sh_gs[g]; bi = g; }
            }
            used[bi] = true;
            keep |= (1u << bi);
        }
        sh_keep = keep;
    }
    __syncthreads();

    sh_val[e] = ((sh_keep >> wid) & 1u) ? s : -INFINITY;
    __syncthreads();

    // --- masked top-8: 8 rounds of block argmax (value desc, index asc) ---
    for (int r = 0; r < TOPKN; r++) {
        float v = sh_val[e];
        int   ix = e;
        #pragma unroll
        for (int o = 16; o > 0; o >>= 1) {
            float ov = __shfl_down_sync(0xffffffffu, v, o);
            int   oi = __shfl_down_sync(0xffffffffu, ix, o);
            if (ov > v || (ov == v && oi < ix)) { v = ov; ix = oi; }
        }
        if (lane == 0) { sh_rv[wid] = v; sh_ri[wid] = ix; }
        __syncthreads();
        if (e == 0) {
            float bv = sh_rv[0]; int bi = sh_ri[0];
            for (int g = 1; g < 8; g++) {
                if (sh_rv[g] > bv || (sh_rv[g] == bv && sh_ri[g] < bi)) {
                    bv = sh_rv[g]; bi = sh_ri[g];
                }
            }
            sh_sel[r] = bi;
            sh_win = bi;
        }
        __syncthreads();
        if (e == sh_win) sh_val[e] = -INFINITY;
    }

    __syncthreads();
    if (e == 0) {
        float wsum = 0.0f;
        for (int r = 0; r < TOPKN; r++) wsum += sh_sc[sh_sel[r]];
        sh_wsum = wsum;
    }
    __syncthreads();

    if (e < TOPKN) {
        const int ix = sh_sel[e];
        out_w[(size_t)t * TOPKN + e] = __fdiv_rn(sh_sc[ix], sh_wsum) * 2.5f;
        if (write_idx) out_idx[(size_t)t * TOPKN + e] = (float)ix;
    }
}

// ---------------------------------------------------------------------------
extern "C" void kernel_launch(void* const* d_in, const int* in_sizes, int n_in,
                              void* d_out, int out_size)
{
    const float* x    = (const float*)d_in[0];   // [T, 7168]
    const float* w    = (const float*)d_in[1];   // [256, 7168]
    const float* bias = (const float*)d_in[2];   // [256]

    const int T = in_sizes[0] / DIM;             // 16384

    dim3 grid(T / BM, NEXP / BN);                // (128, 2)
    gemm_logits_kernel<<<grid, 256>>>(x, w);

    float* out = (float*)d_out;
    const int write_idx = (out_size >= 2 * T * TOPKN) ? 1 : 0;
    gate_epilogue_kernel<<<T, 256>>>(bias, out, out + (size_t)T * TOPKN, write_idx);
}

// round 4
// speedup vs baseline: 1.3274x; 1.3274x over previous
#include <cuda_runtime.h>
#include <cuda_bf16.h>
#include <cstdint>
#include <math.h>

#define DIM    7168
#define NEXP   256
#define TOPKN  8
#define NGRP   8
#define TOPG   4

#define BM     128
#define BN     128
#define KCH    32                 // K per chunk
#define NCH    (DIM / KCH)        // 224

#define TROW   80                 // bytes per smem tile row (64 bf16 + pad) -> 5 mod 8 bank groups
#define TILEB  (128 * TROW)       // 10240 B per split tile (rows = 128 for A(tokens) / B(experts))
#define STAGEB (6 * TILEB)        // Ah Am Al Bh Bm Bl = 61440 B
#define SMEMB  (2 * STAGEB)       // 122880 B

#define OFF_AH 0
#define OFF_AM TILEB
#define OFF_AL (2 * TILEB)
#define OFF_BH (3 * TILEB)
#define OFF_BM (4 * TILEB)
#define OFF_BL (5 * TILEB)

__device__ __align__(16) float g_logits[(size_t)16384 * NEXP];

// ---------------------------------------------------------------------------
// helpers
// ---------------------------------------------------------------------------
__device__ __forceinline__ uint32_t smem_u32(const void* p) {
    uint32_t a;
    asm("{ .reg .u64 t; cvta.to.shared.u64 t, %1; cvt.u32.u64 %0, t; }" : "=r"(a) : "l"(p));
    return a;
}

#define LDMATRIX4(r, addr) \
    asm volatile("ldmatrix.sync.aligned.m8n8.x4.shared.b16 {%0,%1,%2,%3}, [%4];" \
        : "=r"((r)[0]), "=r"((r)[1]), "=r"((r)[2]), "=r"((r)[3]) : "r"(addr))

#define MMA16816(d, a, b0v, b1v) \
    asm volatile("mma.sync.aligned.m16n8k16.row.col.f32.bf16.bf16.f32 " \
        "{%0,%1,%2,%3}, {%4,%5,%6,%7}, {%8,%9}, {%0,%1,%2,%3};" \
        : "+f"((d)[0]), "+f"((d)[1]), "+f"((d)[2]), "+f"((d)[3]) \
        : "r"((a)[0]), "r"((a)[1]), "r"((a)[2]), "r"((a)[3]), "r"(b0v), "r"(b1v))

// Fast2Sum fold (exact ops via PTX so the compiler can't simplify them away)
__device__ __forceinline__ void fast2sum(float& hi, float& lo) {
    float s, z;
    asm("add.rn.f32 %0, %1, %2;" : "=f"(s) : "f"(hi), "f"(lo));
    asm("sub.rn.f32 %0, %1, %2;" : "=f"(z) : "f"(s), "f"(hi));
    asm("sub.rn.f32 %0, %1, %2;" : "=f"(lo) : "f"(lo), "f"(z));
    hi = s;
}

// Exact 3-way bf16 split of 2 fp32 values -> three bf16x2 (elem0 in low 16).
__device__ __forceinline__ void split2(float e0, float e1,
                                       uint32_t& H, uint32_t& M, uint32_t& L) {
    asm("cvt.rn.bf16x2.f32 %0, %1, %2;" : "=r"(H) : "f"(e1), "f"(e0));
    float h0 = __uint_as_float(H << 16);
    float h1 = __uint_as_float(H & 0xffff0000u);
    float r0 = e0 - h0, r1 = e1 - h1;
    asm("cvt.rn.bf16x2.f32 %0, %1, %2;" : "=r"(M) : "f"(r1), "f"(r0));
    float m0 = __uint_as_float(M << 16);
    float m1 = __uint_as_float(M & 0xffff0000u);
    float s0 = r0 - m0, s1 = r1 - m1;
    asm("cvt.rn.bf16x2.f32 %0, %1, %2;" : "=r"(L) : "f"(s1), "f"(s0));
}

__device__ __forceinline__ void split8(const float4& v0, const float4& v1,
                                       uint4& H, uint4& M, uint4& L) {
    split2(v0.x, v0.y, H.x, M.x, L.x);
    split2(v0.z, v0.w, H.y, M.y, L.y);
    split2(v1.x, v1.y, H.z, M.z, L.z);
    split2(v1.z, v1.w, H.w, M.w, L.w);
}

// ---------------------------------------------------------------------------
// GEMM: logits = x @ w^T. bf16 HMMA (mma.sync), exact 3-split, 6 passes,
// Fast2Sum-compensated chunk accumulation.
// ---------------------------------------------------------------------------
extern __shared__ char dynsmem[];

__global__ void __launch_bounds__(256)
gemm_hmma_kernel(const float* __restrict__ x, const float* __restrict__ w)
{
    const int bm   = blockIdx.x;
    const int bn   = blockIdx.y;
    const int tid  = threadIdx.x;
    const int lane = tid & 31;
    const int wid  = tid >> 5;
    const int warp_m = wid >> 1;     // 0..3 -> rows warp_m*32
    const int warp_n = wid & 1;      // 0..1 -> cols warp_n*64

    const uint32_t smem = smem_u32(dynsmem);

    const float* xb = x + (size_t)(bm * BM) * DIM;
    const float* wb = w + (size_t)(bn * BN) * DIM;

    // loader indices: slot j covers rows row0 + 64*j, unit kg (8 fp32 = 16B bf16)
    const int row0 = tid >> 2;       // 0..63
    const int kg   = tid & 3;        // 0..3

    float acc[2][8][4];              // chunk accumulator
    float hiv[2][8][4];              // master (Fast2Sum)
    #pragma unroll
    for (int a = 0; a < 2; a++)
        #pragma unroll
        for (int n = 0; n < 8; n++)
            #pragma unroll
            for (int r = 0; r < 4; r++) { acc[a][n][r] = 0.0f; hiv[a][n][r] = 0.0f; }

    float4 pf[8];

    // ---- prologue: chunk 0 ----
    {
        const int kbase = 0;
        #pragma unroll
        for (int j = 0; j < 2; j++) {
            const float* px = xb + (size_t)(row0 + 64 * j) * DIM + kbase + kg * 8;
            pf[j * 2]     = *reinterpret_cast<const float4*>(px);
            pf[j * 2 + 1] = *reinterpret_cast<const float4*>(px + 4);
            const float* pw = wb + (size_t)(row0 + 64 * j) * DIM + kbase + kg * 8;
            pf[4 + j * 2]     = *reinterpret_cast<const float4*>(pw);
            pf[4 + j * 2 + 1] = *reinterpret_cast<const float4*>(pw + 4);
        }
        #pragma unroll
        for (int j = 0; j < 2; j++) {
            const int row = row0 + 64 * j;
            const int off = row * TROW + kg * 16;
            uint4 H, M, L;
            split8(pf[j * 2], pf[j * 2 + 1], H, M, L);
            *reinterpret_cast<uint4*>(dynsmem + OFF_AH + off) = H;
            *reinterpret_cast<uint4*>(dynsmem + OFF_AM + off) = M;
            *reinterpret_cast<uint4*>(dynsmem + OFF_AL + off) = L;
            split8(pf[4 + j * 2], pf[4 + j * 2 + 1], H, M, L);
            *reinterpret_cast<uint4*>(dynsmem + OFF_BH + off) = H;
            *reinterpret_cast<uint4*>(dynsmem + OFF_BM + off) = M;
            *reinterpret_cast<uint4*>(dynsmem + OFF_BL + off) = L;
        }
    }
    __syncthreads();

    for (int c = 0; c < NCH; ++c) {
        const uint32_t stage = smem + (uint32_t)(c & 1) * STAGEB;

        // ---- prefetch next chunk into registers (hidden under mma) ----
        if (c + 1 < NCH) {
            const int kbase = (c + 1) * KCH;
            #pragma unroll
            for (int j = 0; j < 2; j++) {
                const float* px = xb + (size_t)(row0 + 64 * j) * DIM + kbase + kg * 8;
                pf[j * 2]     = *reinterpret_cast<const float4*>(px);
                pf[j * 2 + 1] = *reinterpret_cast<const float4*>(px + 4);
                const float* pw = wb + (size_t)(row0 + 64 * j) * DIM + kbase + kg * 8;
                pf[4 + j * 2]     = *reinterpret_cast<const float4*>(pw);
                pf[4 + j * 2 + 1] = *reinterpret_cast<const float4*>(pw + 4);
            }
        }

        // ---- mma over this chunk: ks = 0,1 (k=16 each), 6 passes ----
        #pragma unroll
        for (int ks = 0; ks < 2; ++ks) {
            uint32_t ah[2][4], am_[2][4], al[2][4];
            #pragma unroll
            for (int amz = 0; amz < 2; ++amz) {
                const int row = warp_m * 32 + amz * 16 + (lane & 15);
                const int u   = ks * 2 + (lane >> 4);
                const uint32_t ad = stage + row * TROW + u * 16;
                LDMATRIX4(ah[amz],  ad + OFF_AH);
                LDMATRIX4(am_[amz], ad + OFF_AM);
                LDMATRIX4(al[amz],  ad + OFF_AL);
            }
            #pragma unroll
            for (int pair = 0; pair < 4; ++pair) {
                const int brow = warp_n * 64 + pair * 16 + (lane & 7) + ((lane >> 4) << 3);
                const int u    = ks * 2 + ((lane >> 3) & 1);
                const uint32_t bd = stage + brow * TROW + u * 16;
                uint32_t bh[4], bmf[4], blf[4];
                LDMATRIX4(bh,  bd + OFF_BH);
                LDMATRIX4(bmf, bd + OFF_BM);
                LDMATRIX4(blf, bd + OFF_BL);
                #pragma unroll
                for (int amz = 0; amz < 2; ++amz)
                    #pragma unroll
                    for (int bo = 0; bo < 2; ++bo) {
                        float* d = acc[amz][pair * 2 + bo];
                        MMA16816(d, ah[amz],  bh[2*bo],  bh[2*bo+1]);   // hh
                        MMA16816(d, ah[amz],  bmf[2*bo], bmf[2*bo+1]);  // hm
                        MMA16816(d, am_[amz], bh[2*bo],  bh[2*bo+1]);   // mh
                        MMA16816(d, ah[amz],  blf[2*bo], blf[2*bo+1]);  // hl
                        MMA16816(d, al[amz],  bh[2*bo],  bh[2*bo+1]);   // lh
                        MMA16816(d, am_[amz], bmf[2*bo], bmf[2*bo+1]);  // mm
                    }
            }
        }

        // ---- split + store next chunk to the other stage ----
        if (c + 1 < NCH) {
            char* other = dynsmem + ((c + 1) & 1) * STAGEB;
            #pragma unroll
            for (int j = 0; j < 2; j++) {
                const int row = row0 + 64 * j;
                const int off = row * TROW + kg * 16;
                uint4 H, M, L;
                split8(pf[j * 2], pf[j * 2 + 1], H, M, L);
                *reinterpret_cast<uint4*>(other + OFF_AH + off) = H;
                *reinterpret_cast<uint4*>(other + OFF_AM + off) = M;
                *reinterpret_cast<uint4*>(other + OFF_AL + off) = L;
                split8(pf[4 + j * 2], pf[4 + j * 2 + 1], H, M, L);
                *reinterpret_cast<uint4*>(other + OFF_BH + off) = H;
                *reinterpret_cast<uint4*>(other + OFF_BM + off) = M;
                *reinterpret_cast<uint4*>(other + OFF_BL + off) = L;
            }
        }

        // ---- Fast2Sum fold: master += chunk; residual seeds next chunk ----
        #pragma unroll
        for (int a = 0; a < 2; a++)
            #pragma unroll
            for (int n = 0; n < 8; n++)
                #pragma unroll
                for (int r = 0; r < 4; r++)
                    fast2sum(hiv[a][n][r], acc[a][n][r]);

        __syncthreads();
    }

    // ---- write logits ----
    #pragma unroll
    for (int amz = 0; amz < 2; ++amz) {
        const int token = bm * BM + warp_m * 32 + amz * 16 + (lane >> 2);
        #pragma unroll
        for (int n = 0; n < 8; ++n) {
            const int expert = bn * BN + warp_n * 64 + n * 8 + (lane & 3) * 2;
            float d0 = hiv[amz][n][0] + acc[amz][n][0];
            float d1 = hiv[amz][n][1] + acc[amz][n][1];
            float d2 = hiv[amz][n][2] + acc[amz][n][2];
            float d3 = hiv[amz][n][3] + acc[amz][n][3];
            *reinterpret_cast<float2*>(&g_logits[(size_t)token * NEXP + expert]) =
                make_float2(d0, d1);
            *reinterpret_cast<float2*>(&g_logits[(size_t)(token + 8) * NEXP + expert]) =
                make_float2(d2, d3);
        }
    }
}

// ---------------------------------------------------------------------------
// Accurate exp (~2 ulp), immune to fast-math.
// ---------------------------------------------------------------------------
__device__ __forceinline__ float exp_acc(float xin) {
    float xc = fminf(fmaxf(xin, -30.0f), 30.0f);
    float k = rintf(xc * 1.4426950408889634f);
    float r = fmaf(k, -0.693359375f, xc);
    r = fmaf(k, 2.12194440054690e-4f, r);
    float p = 1.98412698e-4f;
    p = fmaf(p, r, 1.38888889e-3f);
    p = fmaf(p, r, 8.33333333e-3f);
    p = fmaf(p, r, 4.16666667e-2f);
    p = fmaf(p, r, 1.66666667e-1f);
    p = fmaf(p, r, 5.0e-1f);
    p = fmaf(p, r, 1.0f);
    p = fmaf(p, r, 1.0f);
    int ik = (int)k;
    float sc2 = __int_as_float((ik + 127) << 23);
    return p * sc2;
}

// ---------------------------------------------------------------------------
// Epilogue: one CTA (256 threads) per token (verified in round 2).
// ---------------------------------------------------------------------------
__global__ void __launch_bounds__(256)
gate_epilogue_kernel(const float* __restrict__ bias,
                     float* __restrict__ out_w,
                     float* __restrict__ out_idx,
                     int write_idx)
{
    const int t    = blockIdx.x;
    const int e    = threadIdx.x;
    const int lane = e & 31;
    const int wid  = e >> 5;

    __shared__ float sh_sc[NEXP];
    __shared__ float sh_val[NEXP];
    __shared__ float sh_gs[NGRP];
    __shared__ float sh_rv[8];
    __shared__ int   sh_ri[8];
    __shared__ int   sh_sel[TOPKN];
    __shared__ int   sh_win;
    __shared__ unsigned sh_keep;
    __shared__ float sh_wsum;

    const float logit = g_logits[(size_t)t * NEXP + e];
    const float sc = __fdiv_rn(1.0f, 1.0f + exp_acc(-logit));
    const float s  = sc + bias[e];
    sh_sc[e] = sc;

    float v1 = s, v2 = -INFINITY;
    #pragma unroll
    for (int o = 16; o > 0; o >>= 1) {
        float u1 = __shfl_down_sync(0xffffffffu, v1, o);
        float u2 = __shfl_down_sync(0xffffffffu, v2, o);
        float hi = fmaxf(v1, u1);
        float lo = fminf(v1, u1);
        float wsec = (v1 >= u1) ? v2 : u2;
        v1 = hi;
        v2 = fmaxf(lo, wsec);
    }
    if (lane == 0) sh_gs[wid] = v1 + v2;
    __syncthreads();

    if (e == 0) {
        unsigned keep = 0;
        bool used[NGRP] = {false, false, false, false, false, false, false, false};
        for (int r = 0; r < TOPG; r++) {
            float best = -INFINITY; int bi = 0;
            for (int g = 0; g < NGRP; g++) {
                if (!used[g] && sh_gs[g] > best) { best = sh_gs[g]; bi = g; }
            }
            used[bi] = true;
            keep |= (1u << bi);
        }
        sh_keep = keep;
    }
    __syncthreads();

    sh_val[e] = ((sh_keep >> wid) & 1u) ? s : -INFINITY;
    __syncthreads();

    for (int r = 0; r < TOPKN; r++) {
        float v = sh_val[e];
        int   ix = e;
        #pragma unroll
        for (int o = 16; o > 0; o >>= 1) {
            float ov = __shfl_down_sync(0xffffffffu, v, o);
            int   oi = __shfl_down_sync(0xffffffffu, ix, o);
            if (ov > v || (ov == v && oi < ix)) { v = ov; ix = oi; }
        }
        if (lane == 0) { sh_rv[wid] = v; sh_ri[wid] = ix; }
        __syncthreads();
        if (e == 0) {
            float bv = sh_rv[0]; int bi = sh_ri[0];
            for (int g = 1; g < 8; g++) {
                if (sh_rv[g] > bv || (sh_rv[g] == bv && sh_ri[g] < bi)) {
                    bv = sh_rv[g]; bi = sh_ri[g];
                }
            }
            sh_sel[r] = bi;
            sh_win = bi;
        }
        __syncthreads();
        if (e == sh_win) sh_val[e] = -INFINITY;
    }

    __syncthreads();
    if (e == 0) {
        float wsum = 0.0f;
        for (int r = 0; r < TOPKN; r++) wsum += sh_sc[sh_sel[r]];
        sh_wsum = wsum;
    }
    __syncthreads();

    if (e < TOPKN) {
        const int ix = sh_sel[e];
        out_w[(size_t)t * TOPKN + e] = __fdiv_rn(sh_sc[ix], sh_wsum) * 2.5f;
        if (write_idx) out_idx[(size_t)t * TOPKN + e] = (float)ix;
    }
}

// ---------------------------------------------------------------------------
extern "C" void kernel_launch(void* const* d_in, const int* in_sizes, int n_in,
                              void* d_out, int out_size)
{
    const float* x    = (const float*)d_in[0];   // [T, 7168]
    const float* w    = (const float*)d_in[1];   // [256, 7168]
    const float* bias = (const float*)d_in[2];   // [256]

    const int T = in_sizes[0] / DIM;             // 16384

    cudaFuncSetAttribute(gemm_hmma_kernel,
                         cudaFuncAttributeMaxDynamicSharedMemorySize, SMEMB);

    dim3 grid(T / BM, NEXP / BN);                // (128, 2)
    gemm_hmma_kernel<<<grid, 256, SMEMB>>>(x, w);

    float* out = (float*)d_out;
    const int write_idx = (out_size >= 2 * T * TOPKN) ? 1 : 0;
    gate_epilogue_kernel<<<T, 256>>>(bias, out, out + (size_t)T * TOPKN, write_idx);
}

// round 5
// speedup vs baseline: 1.4487x; 1.0914x over previous
#include <cuda_runtime.h>
#include <cuda_fp16.h>
#include <cstdint>
#include <math.h>

#define DIM    7168
#define NEXP   256
#define TOPKN  8
#define NGRP   8
#define TOPG   4

#define BM     128
#define BN     128
#define KCH    64                 // K per chunk
#define NCH    (DIM / KCH)        // 112

#define TROW   144                // 64 fp16 = 128B + 16B pad -> 9 mod 8 (16B units): conflict-free
#define TILEB  (128 * TROW)       // 18432 B
#define STAGEB (4 * TILEB)        // Ah Al Bh Bl = 73728 B
#define SMEMB  (2 * STAGEB)       // 147456 B

#define OFF_AH 0
#define OFF_AL TILEB
#define OFF_BH (2 * TILEB)
#define OFF_BL (3 * TILEB)

#define W_SCALE   64.0f
#define INV_SCALE 0.015625f

__device__ __align__(16) float g_logits[(size_t)16384 * NEXP];

// ---------------------------------------------------------------------------
// helpers
// ---------------------------------------------------------------------------
__device__ __forceinline__ uint32_t smem_u32(const void* p) {
    uint32_t a;
    asm("{ .reg .u64 t; cvta.to.shared.u64 t, %1; cvt.u32.u64 %0, t; }" : "=r"(a) : "l"(p));
    return a;
}

#define LDMATRIX4(r, addr) \
    asm volatile("ldmatrix.sync.aligned.m8n8.x4.shared.b16 {%0,%1,%2,%3}, [%4];" \
        : "=r"((r)[0]), "=r"((r)[1]), "=r"((r)[2]), "=r"((r)[3]) : "r"(addr))

#define MMA16816F16(d, a, b0v, b1v) \
    asm volatile("mma.sync.aligned.m16n8k16.row.col.f32.f16.f16.f32 " \
        "{%0,%1,%2,%3}, {%4,%5,%6,%7}, {%8,%9}, {%0,%1,%2,%3};" \
        : "+f"((d)[0]), "+f"((d)[1]), "+f"((d)[2]), "+f"((d)[3]) \
        : "r"((a)[0]), "r"((a)[1]), "r"((a)[2]), "r"((a)[3]), "r"(b0v), "r"(b1v))

// Fast2Sum fold (exact PTX so the compiler can't simplify)
__device__ __forceinline__ void fast2sum(float& hi, float& lo) {
    float s, z;
    asm("add.rn.f32 %0, %1, %2;" : "=f"(s) : "f"(hi), "f"(lo));
    asm("sub.rn.f32 %0, %1, %2;" : "=f"(z) : "f"(s), "f"(hi));
    asm("sub.rn.f32 %0, %1, %2;" : "=f"(lo) : "f"(lo), "f"(z));
    hi = s;
}

// 2-way fp16 split of 2 fp32 -> two f16x2 (elem0 in low 16)
__device__ __forceinline__ void splitf16_2(float e0, float e1, uint32_t& H, uint32_t& L) {
    __half2 h = __floats2half2_rn(e0, e1);
    float2 hf = __half22float2(h);
    __half2 l = __floats2half2_rn(e0 - hf.x, e1 - hf.y);
    H = *reinterpret_cast<uint32_t*>(&h);
    L = *reinterpret_cast<uint32_t*>(&l);
}

// 8 fp32 (two float4, scaled by sc) -> uint4 H, uint4 L
__device__ __forceinline__ void split8(float4 v0, float4 v1, float sc,
                                       uint4& H, uint4& L) {
    splitf16_2(v0.x * sc, v0.y * sc, H.x, L.x);
    splitf16_2(v0.z * sc, v0.w * sc, H.y, L.y);
    splitf16_2(v1.x * sc, v1.y * sc, H.z, L.z);
    splitf16_2(v1.z * sc, v1.w * sc, H.w, L.w);
}

// ---------------------------------------------------------------------------
// GEMM: logits = x @ (64*w)^T / 64.  fp16 HMMA, exact 2-split, 3 passes
// (hh + hl + lh; ll term ~2^-24 dropped), Fast2Sum-compensated accumulation.
// ---------------------------------------------------------------------------
extern __shared__ char dynsmem[];

__global__ void __launch_bounds__(256)
gemm_hmma_kernel(const float* __restrict__ x, const float* __restrict__ w)
{
    const int bm   = blockIdx.x;
    const int bn   = blockIdx.y;
    const int tid  = threadIdx.x;
    const int lane = tid & 31;
    const int wid  = tid >> 5;
    const int warp_m = wid >> 1;     // 0..3 -> token rows warp_m*32
    const int warp_n = wid & 1;      // 0..1 -> expert cols warp_n*64

    const uint32_t smem = smem_u32(dynsmem);

    const float* xb = x + (size_t)(bm * BM) * DIM;
    const float* wb = w + (size_t)(bn * BN) * DIM;

    // loader: each thread owns one row-half: 32 floats = 8 float4
    const int lrow  = tid >> 1;      // 0..127
    const int lhalf = tid & 1;       // 0..1 (cols lhalf*32 .. +32)

    float acc[2][8][4];
    float hiv[2][8][4];
    #pragma unroll
    for (int a = 0; a < 2; a++)
        #pragma unroll
        for (int n = 0; n < 8; n++)
            #pragma unroll
            for (int r = 0; r < 4; r++) { acc[a][n][r] = 0.0f; hiv[a][n][r] = 0.0f; }

    float4 pfx[8], pfw[8];

    // ---- prologue: load + split + store chunk 0 ----
    {
        const float* px = xb + (size_t)lrow * DIM + lhalf * 32;
        const float* pw = wb + (size_t)lrow * DIM + lhalf * 32;
        #pragma unroll
        for (int q = 0; q < 8; q++) pfx[q] = *reinterpret_cast<const float4*>(px + q * 4);
        #pragma unroll
        for (int q = 0; q < 8; q++) pfw[q] = *reinterpret_cast<const float4*>(pw + q * 4);
        const int off = lrow * TROW + lhalf * 64;
        #pragma unroll
        for (int j = 0; j < 4; j++) {
            uint4 H, L;
            split8(pfx[2 * j], pfx[2 * j + 1], 1.0f, H, L);
            *reinterpret_cast<uint4*>(dynsmem + OFF_AH + off + j * 16) = H;
            *reinterpret_cast<uint4*>(dynsmem + OFF_AL + off + j * 16) = L;
            split8(pfw[2 * j], pfw[2 * j + 1], W_SCALE, H, L);
            *reinterpret_cast<uint4*>(dynsmem + OFF_BH + off + j * 16) = H;
            *reinterpret_cast<uint4*>(dynsmem + OFF_BL + off + j * 16) = L;
        }
    }
    __syncthreads();

    for (int c = 0; c < NCH; ++c) {
        const uint32_t stage = smem + (uint32_t)(c & 1) * STAGEB;
        const bool more = (c + 1 < NCH);

        // prefetch next x early (DRAM-latency class)
        if (more) {
            const float* px = xb + (size_t)lrow * DIM + (c + 1) * KCH + lhalf * 32;
            #pragma unroll
            for (int q = 0; q < 8; q++) pfx[q] = *reinterpret_cast<const float4*>(px + q * 4);
        }

        // ---- mma over this chunk: 4 k16 steps, 3 passes ----
        #pragma unroll
        for (int ks = 0; ks < 4; ++ks) {
            uint32_t ah[2][4], al[2][4];
            #pragma unroll
            for (int amz = 0; amz < 2; ++amz) {
                const int row = warp_m * 32 + amz * 16 + (lane & 15);
                const int u   = ks * 2 + (lane >> 4);
                const uint32_t ad = stage + row * TROW + u * 16;
                LDMATRIX4(ah[amz], ad + OFF_AH);
                LDMATRIX4(al[amz], ad + OFF_AL);
            }
            // w prefetch mid-chunk (L2-hot: 256 rows shared by all bm tiles)
            if (ks == 2 && more) {
                const float* pw = wb + (size_t)lrow * DIM + (c + 1) * KCH + lhalf * 32;
                #pragma unroll
                for (int q = 0; q < 8; q++) pfw[q] = *reinterpret_cast<const float4*>(pw + q * 4);
            }
            #pragma unroll
            for (int pair = 0; pair < 4; ++pair) {
                const int brow = warp_n * 64 + pair * 16 + (lane & 7) + ((lane >> 4) << 3);
                const int u    = ks * 2 + ((lane >> 3) & 1);
                const uint32_t bd = stage + brow * TROW + u * 16;
                uint32_t bh[4], bl[4];
                LDMATRIX4(bh, bd + OFF_BH);
                LDMATRIX4(bl, bd + OFF_BL);
                #pragma unroll
                for (int amz = 0; amz < 2; ++amz)
                    #pragma unroll
                    for (int bo = 0; bo < 2; ++bo) {
                        float* d = acc[amz][pair * 2 + bo];
                        MMA16816F16(d, ah[amz], bh[2*bo], bh[2*bo+1]);   // hh
                        MMA16816F16(d, ah[amz], bl[2*bo], bl[2*bo+1]);   // hl
                        MMA16816F16(d, al[amz], bh[2*bo], bh[2*bo+1]);   // lh
                    }
            }
        }

        // ---- split + store next chunk into the other stage ----
        if (more) {
            char* other = dynsmem + ((c + 1) & 1) * STAGEB;
            const int off = lrow * TROW + lhalf * 64;
            #pragma unroll
            for (int j = 0; j < 4; j++) {
                uint4 H, L;
                split8(pfx[2 * j], pfx[2 * j + 1], 1.0f, H, L);
                *reinterpret_cast<uint4*>(other + OFF_AH + off + j * 16) = H;
                *reinterpret_cast<uint4*>(other + OFF_AL + off + j * 16) = L;
                split8(pfw[2 * j], pfw[2 * j + 1], W_SCALE, H, L);
                *reinterpret_cast<uint4*>(other + OFF_BH + off + j * 16) = H;
                *reinterpret_cast<uint4*>(other + OFF_BL + off + j * 16) = L;
            }
        }

        // ---- Fast2Sum fold every 2 chunks ----
        if (c & 1) {
            #pragma unroll
            for (int a = 0; a < 2; a++)
                #pragma unroll
                for (int n = 0; n < 8; n++)
                    #pragma unroll
                    for (int r = 0; r < 4; r++)
                        fast2sum(hiv[a][n][r], acc[a][n][r]);
        }

        __syncthreads();
    }

    // ---- write logits (undo W scale) ----
    #pragma unroll
    for (int amz = 0; amz < 2; ++amz) {
        const int token = bm * BM + warp_m * 32 + amz * 16 + (lane >> 2);
        #pragma unroll
        for (int n = 0; n < 8; ++n) {
            const int expert = bn * BN + warp_n * 64 + n * 8 + (lane & 3) * 2;
            float d0 = (hiv[amz][n][0] + acc[amz][n][0]) * INV_SCALE;
            float d1 = (hiv[amz][n][1] + acc[amz][n][1]) * INV_SCALE;
            float d2 = (hiv[amz][n][2] + acc[amz][n][2]) * INV_SCALE;
            float d3 = (hiv[amz][n][3] + acc[amz][n][3]) * INV_SCALE;
            *reinterpret_cast<float2*>(&g_logits[(size_t)token * NEXP + expert]) =
                make_float2(d0, d1);
            *reinterpret_cast<float2*>(&g_logits[(size_t)(token + 8) * NEXP + expert]) =
                make_float2(d2, d3);
        }
    }
}

// ---------------------------------------------------------------------------
// Accurate exp (~2 ulp), immune to fast-math.
// ---------------------------------------------------------------------------
__device__ __forceinline__ float exp_acc(float xin) {
    float xc = fminf(fmaxf(xin, -30.0f), 30.0f);
    float k = rintf(xc * 1.4426950408889634f);
    float r = fmaf(k, -0.693359375f, xc);
    r = fmaf(k, 2.12194440054690e-4f, r);
    float p = 1.98412698e-4f;
    p = fmaf(p, r, 1.38888889e-3f);
    p = fmaf(p, r, 8.33333333e-3f);
    p = fmaf(p, r, 4.16666667e-2f);
    p = fmaf(p, r, 1.66666667e-1f);
    p = fmaf(p, r, 5.0e-1f);
    p = fmaf(p, r, 1.0f);
    p = fmaf(p, r, 1.0f);
    int ik = (int)k;
    float sc2 = __int_as_float((ik + 127) << 23);
    return p * sc2;
}

// ---------------------------------------------------------------------------
// Epilogue: one CTA (256 threads) per token (verified rounds 2/4).
// ---------------------------------------------------------------------------
__global__ void __launch_bounds__(256)
gate_epilogue_kernel(const float* __restrict__ bias,
                     float* __restrict__ out_w,
                     float* __restrict__ out_idx,
                     int write_idx)
{
    const int t    = blockIdx.x;
    const int e    = threadIdx.x;
    const int lane = e & 31;
    const int wid  = e >> 5;

    __shared__ float sh_sc[NEXP];
    __shared__ float sh_val[NEXP];
    __shared__ float sh_gs[NGRP];
    __shared__ float sh_rv[8];
    __shared__ int   sh_ri[8];
    __shared__ int   sh_sel[TOPKN];
    __shared__ int   sh_win;
    __shared__ unsigned sh_keep;
    __shared__ float sh_wsum;

    const float logit = g_logits[(size_t)t * NEXP + e];
    const float sc = __fdiv_rn(1.0f, 1.0f + exp_acc(-logit));
    const float s  = sc + bias[e];
    sh_sc[e] = sc;

    float v1 = s, v2 = -INFINITY;
    #pragma unroll
    for (int o = 16; o > 0; o >>= 1) {
        float u1 = __shfl_down_sync(0xffffffffu, v1, o);
        float u2 = __shfl_down_sync(0xffffffffu, v2, o);
        float hi = fmaxf(v1, u1);
        float lo = fminf(v1, u1);
        float wsec = (v1 >= u1) ? v2 : u2;
        v1 = hi;
        v2 = fmaxf(lo, wsec);
    }
    if (lane == 0) sh_gs[wid] = v1 + v2;
    __syncthreads();

    if (e == 0) {
        unsigned keep = 0;
        bool used[NGRP] = {false, false, false, false, false, false, false, false};
        for (int r = 0; r < TOPG; r++) {
            float best = -INFINITY; int bi = 0;
            for (int g = 0; g < NGRP; g++) {
                if (!used[g] && sh_gs[g] > best) { best = sh_gs[g]; bi = g; }
            }
            used[bi] = true;
            keep |= (1u << bi);
        }
        sh_keep = keep;
    }
    __syncthreads();

    sh_val[e] = ((sh_keep >> wid) & 1u) ? s : -INFINITY;
    __syncthreads();

    for (int r = 0; r < TOPKN; r++) {
        float v = sh_val[e];
        int   ix = e;
        #pragma unroll
        for (int o = 16; o > 0; o >>= 1) {
            float ov = __shfl_down_sync(0xffffffffu, v, o);
            int   oi = __shfl_down_sync(0xffffffffu, ix, o);
            if (ov > v || (ov == v && oi < ix)) { v = ov; ix = oi; }
        }
        if (lane == 0) { sh_rv[wid] = v; sh_ri[wid] = ix; }
        __syncthreads();
        if (e == 0) {
            float bv = sh_rv[0]; int bi = sh_ri[0];
            for (int g = 1; g < 8; g++) {
                if (sh_rv[g] > bv || (sh_rv[g] == bv && sh_ri[g] < bi)) {
                    bv = sh_rv[g]; bi = sh_ri[g];
                }
            }
            sh_sel[r] = bi;
            sh_win = bi;
        }
        __syncthreads();
        if (e == sh_win) sh_val[e] = -INFINITY;
    }

    __syncthreads();
    if (e == 0) {
        float wsum = 0.0f;
        for (int r = 0; r < TOPKN; r++) wsum += sh_sc[sh_sel[r]];
        sh_wsum = wsum;
    }
    __syncthreads();

    if (e < TOPKN) {
        const int ix = sh_sel[e];
        out_w[(size_t)t * TOPKN + e] = __fdiv_rn(sh_sc[ix], sh_wsum) * 2.5f;
        if (write_idx) out_idx[(size_t)t * TOPKN + e] = (float)ix;
    }
}

// ---------------------------------------------------------------------------
extern "C" void kernel_launch(void* const* d_in, const int* in_sizes, int n_in,
                              void* d_out, int out_size)
{
    const float* x    = (const float*)d_in[0];   // [T, 7168]
    const float* w    = (const float*)d_in[1];   // [256, 7168]
    const float* bias = (const float*)d_in[2];   // [256]

    const int T = in_sizes[0] / DIM;             // 16384

    cudaFuncSetAttribute(gemm_hmma_kernel,
                         cudaFuncAttributeMaxDynamicSharedMemorySize, SMEMB);

    dim3 grid(T / BM, NEXP / BN);                // (128, 2)
    gemm_hmma_kernel<<<grid, 256, SMEMB>>>(x, w);

    float* out = (float*)d_out;
    const int write_idx = (out_size >= 2 * T * TOPKN) ? 1 : 0;
    gate_epilogue_kernel<<<T, 256>>>(bias, out, out + (size_t)T * TOPKN, write_idx);
}

// round 6
// speedup vs baseline: 1.9015x; 1.3125x over previous
#include <cuda_runtime.h>
#include <cuda_fp16.h>
#include <cstdint>
#include <math.h>

#define DIM    7168
#define NEXP   256
#define NTOK   16384
#define TOPKN  8
#define NGRP   8
#define TOPG   4

#define BM     128
#define BN     128
#define KCH    64                 // K per chunk
#define NCH    (DIM / KCH)        // 112
#define NSTAGE 3

#define TROW   144                // 64 fp16 = 128B + 16B pad (conflict-free ldmatrix)
#define TILEB  (128 * TROW)       // 18432 B
#define STAGEB (4 * TILEB)        // Ah Al Bh Bl = 73728 B
#define SMEMB  (NSTAGE * STAGEB)  // 221184 B

#define OFF_AH 0
#define OFF_AL TILEB
#define OFF_BH (2 * TILEB)
#define OFF_BL (3 * TILEB)

#define W_SCALE   64.0f
#define INV_SCALE 0.015625f

// Global scratch (allocation-free): pre-split fp16 operands + logits.
__device__ __align__(16) __half g_xh[(size_t)NTOK * DIM];
__device__ __align__(16) __half g_xl[(size_t)NTOK * DIM];
__device__ __align__(16) __half g_wh[(size_t)NEXP * DIM];
__device__ __align__(16) __half g_wl[(size_t)NEXP * DIM];
__device__ __align__(16) float  g_logits[(size_t)NTOK * NEXP];

// ---------------------------------------------------------------------------
// helpers
// ---------------------------------------------------------------------------
__device__ __forceinline__ uint32_t smem_u32(const void* p) {
    uint32_t a;
    asm("{ .reg .u64 t; cvta.to.shared.u64 t, %1; cvt.u32.u64 %0, t; }" : "=r"(a) : "l"(p));
    return a;
}

__device__ __forceinline__ void cp16(uint32_t dst, const void* src) {
    asm volatile("cp.async.cg.shared.global [%0], [%1], 16;" :: "r"(dst), "l"(src));
}
#define CP_COMMIT() asm volatile("cp.async.commit_group;" ::: "memory")
#define CP_WAIT1()  asm volatile("cp.async.wait_group 1;" ::: "memory")

#define LDMATRIX4(r, addr) \
    asm volatile("ldmatrix.sync.aligned.m8n8.x4.shared.b16 {%0,%1,%2,%3}, [%4];" \
        : "=r"((r)[0]), "=r"((r)[1]), "=r"((r)[2]), "=r"((r)[3]) : "r"(addr))

#define MMA16816F16(d, a, b0v, b1v) \
    asm volatile("mma.sync.aligned.m16n8k16.row.col.f32.f16.f16.f32 " \
        "{%0,%1,%2,%3}, {%4,%5,%6,%7}, {%8,%9}, {%0,%1,%2,%3};" \
        : "+f"((d)[0]), "+f"((d)[1]), "+f"((d)[2]), "+f"((d)[3]) \
        : "r"((a)[0]), "r"((a)[1]), "r"((a)[2]), "r"((a)[3]), "r"(b0v), "r"(b1v))

// Fast2Sum fold (exact PTX so the compiler can't simplify)
__device__ __forceinline__ void fast2sum(float& hi, float& lo) {
    float s, z;
    asm("add.rn.f32 %0, %1, %2;" : "=f"(s) : "f"(hi), "f"(lo));
    asm("sub.rn.f32 %0, %1, %2;" : "=f"(z) : "f"(s), "f"(hi));
    asm("sub.rn.f32 %0, %1, %2;" : "=f"(lo) : "f"(lo), "f"(z));
    hi = s;
}

// ---------------------------------------------------------------------------
// Prep: exact 2-way fp16 split of scaled fp32 stream.  h = rn(s*v),
// l = rn(s*v - h) (residual exact by Sterbenz before rounding).
// ---------------------------------------------------------------------------
__global__ void __launch_bounds__(256)
split_prep_kernel(const float* __restrict__ src,
                  __half* __restrict__ hO, __half* __restrict__ lO,
                  float scale, int n4)
{
    const float4* s4 = reinterpret_cast<const float4*>(src);
    int i = blockIdx.x * blockDim.x + threadIdx.x;
    const int stride = gridDim.x * blockDim.x;
    for (; i < n4; i += stride) {
        float4 v = s4[i];
        v.x *= scale; v.y *= scale; v.z *= scale; v.w *= scale;
        __half2 h0 = __floats2half2_rn(v.x, v.y);
        __half2 h1 = __floats2half2_rn(v.z, v.w);
        float2 f0 = __half22float2(h0), f1 = __half22float2(h1);
        __half2 l0 = __floats2half2_rn(v.x - f0.x, v.y - f0.y);
        __half2 l1 = __floats2half2_rn(v.z - f1.x, v.w - f1.y);
        uint2 hv, lv;
        hv.x = *reinterpret_cast<uint32_t*>(&h0);
        hv.y = *reinterpret_cast<uint32_t*>(&h1);
        lv.x = *reinterpret_cast<uint32_t*>(&l0);
        lv.y = *reinterpret_cast<uint32_t*>(&l1);
        *reinterpret_cast<uint2*>(hO + 4 * (size_t)i) = hv;
        *reinterpret_cast<uint2*>(lO + 4 * (size_t)i) = lv;
    }
}

// ---------------------------------------------------------------------------
// GEMM: logits = x @ (64*w)^T / 64.  fp16 HMMA, 3 passes (hh+hl+lh),
// cp.async 3-stage pipeline on pre-split fp16 operands, Fast2Sum accumulate.
// ---------------------------------------------------------------------------
extern __shared__ char dynsmem[];

__global__ void __launch_bounds__(256)
gemm_hmma_kernel()
{
    const int bm   = blockIdx.x;
    const int bn   = blockIdx.y;
    const int tid  = threadIdx.x;
    const int lane = tid & 31;
    const int wid  = tid >> 5;
    const int warp_m = wid >> 1;     // 0..3 -> token rows warp_m*32
    const int warp_n = wid & 1;      // 0..1 -> expert cols warp_n*64

    const uint32_t smem = smem_u32(dynsmem);

    const __half* xh_b = g_xh + (size_t)(bm * BM) * DIM;
    const __half* xl_b = g_xl + (size_t)(bm * BM) * DIM;
    const __half* wh_b = g_wh + (size_t)(bn * BN) * DIM;
    const __half* wl_b = g_wl + (size_t)(bn * BN) * DIM;

    float acc[2][8][4];
    float hiv[2][8][4];
    #pragma unroll
    for (int a = 0; a < 2; a++)
        #pragma unroll
        for (int n = 0; n < 8; n++)
            #pragma unroll
            for (int r = 0; r < 4; r++) { acc[a][n][r] = 0.0f; hiv[a][n][r] = 0.0f; }

    // per-thread cp.async slots: q -> (row, 16B segment)
    auto issue_chunk = [&](int c) {
        const uint32_t sb = smem + (uint32_t)(c % NSTAGE) * STAGEB;
        const int kb = c * KCH;
        #pragma unroll
        for (int t = 0; t < 4; t++) {
            const int q = tid + t * 256;
            const int r = q >> 3;
            const int s = q & 7;
            const uint32_t d = sb + r * TROW + s * 16;
            const size_t go = (size_t)r * DIM + kb + s * 8;
            cp16(d + OFF_AH, xh_b + go);
            cp16(d + OFF_AL, xl_b + go);
            cp16(d + OFF_BH, wh_b + go);
            cp16(d + OFF_BL, wl_b + go);
        }
    };

    issue_chunk(0); CP_COMMIT();
    issue_chunk(1); CP_COMMIT();

    for (int c = 0; c < NCH; ++c) {
        CP_WAIT1();                       // group for chunk c complete
        __syncthreads();                  // data visible; prior stage reads done

        if (c + 2 < NCH) issue_chunk(c + 2);
        CP_COMMIT();                      // always commit (keeps group count in sync)

        const uint32_t stage = smem + (uint32_t)(c % NSTAGE) * STAGEB;

        #pragma unroll
        for (int ks = 0; ks < 4; ++ks) {
            uint32_t ah[2][4], al[2][4];
            #pragma unroll
            for (int amz = 0; amz < 2; ++amz) {
                const int row = warp_m * 32 + amz * 16 + (lane & 15);
                const int u   = ks * 2 + (lane >> 4);
                const uint32_t ad = stage + row * TROW + u * 16;
                LDMATRIX4(ah[amz], ad + OFF_AH);
                LDMATRIX4(al[amz], ad + OFF_AL);
            }
            #pragma unroll
            for (int pair = 0; pair < 4; ++pair) {
                const int brow = warp_n * 64 + pair * 16 + (lane & 7) + ((lane >> 4) << 3);
                const int u    = ks * 2 + ((lane >> 3) & 1);
                const uint32_t bd = stage + brow * TROW + u * 16;
                uint32_t bh[4], bl[4];
                LDMATRIX4(bh, bd + OFF_BH);
                LDMATRIX4(bl, bd + OFF_BL);
                #pragma unroll
                for (int amz = 0; amz < 2; ++amz)
                    #pragma unroll
                    for (int bo = 0; bo < 2; ++bo) {
                        float* d = acc[amz][pair * 2 + bo];
                        MMA16816F16(d, ah[amz], bh[2*bo], bh[2*bo+1]);   // hh
                        MMA16816F16(d, ah[amz], bl[2*bo], bl[2*bo+1]);   // hl
                        MMA16816F16(d, al[amz], bh[2*bo], bh[2*bo+1]);   // lh
                    }
            }
        }

        if (c & 1) {
            #pragma unroll
            for (int a = 0; a < 2; a++)
                #pragma unroll
                for (int n = 0; n < 8; n++)
                    #pragma unroll
                    for (int r = 0; r < 4; r++)
                        fast2sum(hiv[a][n][r], acc[a][n][r]);
        }
    }

    // ---- write logits (undo W scale) ----
    #pragma unroll
    for (int amz = 0; amz < 2; ++amz) {
        const int token = bm * BM + warp_m * 32 + amz * 16 + (lane >> 2);
        #pragma unroll
        for (int n = 0; n < 8; ++n) {
            const int expert = bn * BN + warp_n * 64 + n * 8 + (lane & 3) * 2;
            float d0 = (hiv[amz][n][0] + acc[amz][n][0]) * INV_SCALE;
            float d1 = (hiv[amz][n][1] + acc[amz][n][1]) * INV_SCALE;
            float d2 = (hiv[amz][n][2] + acc[amz][n][2]) * INV_SCALE;
            float d3 = (hiv[amz][n][3] + acc[amz][n][3]) * INV_SCALE;
            *reinterpret_cast<float2*>(&g_logits[(size_t)token * NEXP + expert]) =
                make_float2(d0, d1);
            *reinterpret_cast<float2*>(&g_logits[(size_t)(token + 8) * NEXP + expert]) =
                make_float2(d2, d3);
        }
    }
}

// ---------------------------------------------------------------------------
// Accurate exp (~2 ulp), immune to fast-math.
// ---------------------------------------------------------------------------
__device__ __forceinline__ float exp_acc(float xin) {
    float xc = fminf(fmaxf(xin, -30.0f), 30.0f);
    float k = rintf(xc * 1.4426950408889634f);
    float r = fmaf(k, -0.693359375f, xc);
    r = fmaf(k, 2.12194440054690e-4f, r);
    float p = 1.98412698e-4f;
    p = fmaf(p, r, 1.38888889e-3f);
    p = fmaf(p, r, 8.33333333e-3f);
    p = fmaf(p, r, 4.16666667e-2f);
    p = fmaf(p, r, 1.66666667e-1f);
    p = fmaf(p, r, 5.0e-1f);
    p = fmaf(p, r, 1.0f);
    p = fmaf(p, r, 1.0f);
    int ik = (int)k;
    float sc2 = __int_as_float((ik + 127) << 23);
    return p * sc2;
}

// ---------------------------------------------------------------------------
// Epilogue: one CTA (256 threads) per token (verified rounds 2/4/5).
// ---------------------------------------------------------------------------
__global__ void __launch_bounds__(256)
gate_epilogue_kernel(const float* __restrict__ bias,
                     float* __restrict__ out_w,
                     float* __restrict__ out_idx,
                     int write_idx)
{
    const int t    = blockIdx.x;
    const int e    = threadIdx.x;
    const int lane = e & 31;
    const int wid  = e >> 5;

    __shared__ float sh_sc[NEXP];
    __shared__ float sh_val[NEXP];
    __shared__ float sh_gs[NGRP];
    __shared__ float sh_rv[8];
    __shared__ int   sh_ri[8];
    __shared__ int   sh_sel[TOPKN];
    __shared__ int   sh_win;
    __shared__ unsigned sh_keep;
    __shared__ float sh_wsum;

    const float logit = g_logits[(size_t)t * NEXP + e];
    const float sc = __fdiv_rn(1.0f, 1.0f + exp_acc(-logit));
    const float s  = sc + bias[e];
    sh_sc[e] = sc;

    float v1 = s, v2 = -INFINITY;
    #pragma unroll
    for (int o = 16; o > 0; o >>= 1) {
        float u1 = __shfl_down_sync(0xffffffffu, v1, o);
        float u2 = __shfl_down_sync(0xffffffffu, v2, o);
        float hi = fmaxf(v1, u1);
        float lo = fminf(v1, u1);
        float wsec = (v1 >= u1) ? v2 : u2;
        v1 = hi;
        v2 = fmaxf(lo, wsec);
    }
    if (lane == 0) sh_gs[wid] = v1 + v2;
    __syncthreads();

    if (e == 0) {
        unsigned keep = 0;
        bool used[NGRP] = {false, false, false, false, false, false, false, false};
        for (int r = 0; r < TOPG; r++) {
            float best = -INFINITY; int bi = 0;
            for (int g = 0; g < NGRP; g++) {
                if (!used[g] && sh_gs[g] > best) { best = sh_gs[g]; bi = g; }
            }
            used[bi] = true;
            keep |= (1u << bi);
        }
        sh_keep = keep;
    }
    __syncthreads();

    sh_val[e] = ((sh_keep >> wid) & 1u) ? s : -INFINITY;
    __syncthreads();

    for (int r = 0; r < TOPKN; r++) {
        float v = sh_val[e];
        int   ix = e;
        #pragma unroll
        for (int o = 16; o > 0; o >>= 1) {
            float ov = __shfl_down_sync(0xffffffffu, v, o);
            int   oi = __shfl_down_sync(0xffffffffu, ix, o);
            if (ov > v || (ov == v && oi < ix)) { v = ov; ix = oi; }
        }
        if (lane == 0) { sh_rv[wid] = v; sh_ri[wid] = ix; }
        __syncthreads();
        if (e == 0) {
            float bv = sh_rv[0]; int bi = sh_ri[0];
            for (int g = 1; g < 8; g++) {
                if (sh_rv[g] > bv || (sh_rv[g] == bv && sh_ri[g] < bi)) {
                    bv = sh_rv[g]; bi = sh_ri[g];
                }
            }
            sh_sel[r] = bi;
            sh_win = bi;
        }
        __syncthreads();
        if (e == sh_win) sh_val[e] = -INFINITY;
    }

    __syncthreads();
    if (e == 0) {
        float wsum = 0.0f;
        for (int r = 0; r < TOPKN; r++) wsum += sh_sc[sh_sel[r]];
        sh_wsum = wsum;
    }
    __syncthreads();

    if (e < TOPKN) {
        const int ix = sh_sel[e];
        out_w[(size_t)t * TOPKN + e] = __fdiv_rn(sh_sc[ix], sh_wsum) * 2.5f;
        if (write_idx) out_idx[(size_t)t * TOPKN + e] = (float)ix;
    }
}

// ---------------------------------------------------------------------------
extern "C" void kernel_launch(void* const* d_in, const int* in_sizes, int n_in,
                              void* d_out, int out_size)
{
    const float* x    = (const float*)d_in[0];   // [T, 7168]
    const float* w    = (const float*)d_in[1];   // [256, 7168]
    const float* bias = (const float*)d_in[2];   // [256]

    const int T = in_sizes[0] / DIM;             // 16384

    // resolve device globals (host side, outside capture-restricted ops? —
    // cudaGetSymbolAddress is capture-safe: no alloc, no sync)
    __half *p_xh, *p_xl, *p_wh, *p_wl;
    cudaGetSymbolAddress((void**)&p_xh, g_xh);
    cudaGetSymbolAddress((void**)&p_xl, g_xl);
    cudaGetSymbolAddress((void**)&p_wh, g_wh);
    cudaGetSymbolAddress((void**)&p_wl, g_wl);

    // prep: split x (scale 1) and w (scale 64) into fp16 hi/lo
    split_prep_kernel<<<4096, 256>>>(x, p_xh, p_xl, 1.0f, T * DIM / 4);
    split_prep_kernel<<<256, 256>>>(w, p_wh, p_wl, W_SCALE, NEXP * DIM / 4);

    cudaFuncSetAttribute(gemm_hmma_kernel,
                         cudaFuncAttributeMaxDynamicSharedMemorySize, SMEMB);

    dim3 grid(T / BM, NEXP / BN);                // (128, 2)
    gemm_hmma_kernel<<<grid, 256, SMEMB>>>();

    float* out = (float*)d_out;
    const int write_idx = (out_size >= 2 * T * TOPKN) ? 1 : 0;
    gate_epilogue_kernel<<<T, 256>>>(bias, out, out + (size_t)T * TOPKN, write_idx);
}